// round 5
// baseline (speedup 1.0000x reference)
#include <cuda_runtime.h>
#include <cuda_bf16.h>

// Problem constants (fixed shapes from setup_inputs)
static constexpr int B   = 32;
static constexpr int P   = 32;
static constexpr int S   = 512;
static constexpr int PS  = P * S;        // 16384
static constexpr int NBP = B * P;        // 1024
static constexpr int NPTS = B * PS;      // 524288
static constexpr size_t NOUT = (size_t)B * P * PS;  // 16777216 per output tensor

// Scratch: SoA point table (6 MB) + packed per-(b,p) params.
// par[i*12 + {0..3}] = qn(w,x,y,z); {4..6}=trans; {7..9}=shape; 10=iou; 11=vol
__device__ __align__(16) float g_px[NPTS];
__device__ __align__(16) float g_py[NPTS];
__device__ __align__(16) float g_pz[NPTS];
__device__ __align__(16) float g_par[NBP * 12];

__global__ void prep_kernel(const float* __restrict__ shape,
                            const float* __restrict__ trans,
                            const float* __restrict__ quat,
                            const float* __restrict__ iou) {
    int i = blockIdx.x * blockDim.x + threadIdx.x;
    if (i >= NBP) return;
    float qw = quat[i * 4 + 0];
    float qx = quat[i * 4 + 1];
    float qy = quat[i * 4 + 2];
    float qz = quat[i * 4 + 3];
    float inv = rsqrtf(qw * qw + qx * qx + qy * qy + qz * qz);
    qw *= inv; qx *= inv; qy *= inv; qz *= inv;
    float sx = shape[i * 3 + 0];
    float sy = shape[i * 3 + 1];
    float sz = shape[i * 3 + 2];
    float io = iou[i];
    float* o = &g_par[i * 12];
    o[0] = qw; o[1] = qx; o[2] = qy; o[3] = qz;
    o[4] = trans[i * 3 + 0];
    o[5] = trans[i * 3 + 1];
    o[6] = trans[i * 3 + 2];
    o[7] = sx; o[8] = sy; o[9] = sz;
    o[10] = io;
    o[11] = sx * sy * sz * io;
}

// One thread per point (b, j): forward rotate local coords by owner's quat.
__global__ void points_kernel(const float* __restrict__ coef) {
    int idx = blockIdx.x * blockDim.x + threadIdx.x;   // = b*PS + j
    if (idx >= NPTS) return;
    int b = idx >> 14;            // /PS (PS = 2^14)
    int j = idx & (PS - 1);
    int o = j >> 9;               // /S  (S = 2^9)
    const float* par = &g_par[(b * P + o) * 12];
    float qw = par[0], qx = par[1], qy = par[2], qz = par[3];
    float sx = par[7], sy = par[8], sz = par[9];

    // coef index (b,o,s,c) flattens to idx*3+c
    float vx = fmaf(2.0f, coef[idx * 3 + 0], -1.0f) * sx;
    float vy = fmaf(2.0f, coef[idx * 3 + 1], -1.0f) * sy;
    float vz = fmaf(2.0f, coef[idx * 3 + 2], -1.0f) * sz;

    // quat_rotate: uv = qv x v; uuv = qv x uv; out = v + 2(w*uv + uuv)
    float uvx = qy * vz - qz * vy;
    float uvy = qz * vx - qx * vz;
    float uvz = qx * vy - qy * vx;
    float uuvx = qy * uvz - qz * uvy;
    float uuvy = qz * uvx - qx * uvz;
    float uuvz = qx * uvy - qy * uvx;
    g_px[idx] = vx + 2.0f * (qw * uvx + uuvx) + par[4];
    g_py[idx] = vy + 2.0f * (qw * uvy + uuvy) + par[5];
    g_pz[idx] = vz + 2.0f * (qw * uvz + uuvz) + par[6];
}

// 16 blocks per (b,p); 256 threads/block; 4 j per thread (float4 path).
__global__ void __launch_bounds__(256) tsdf_kernel(float* __restrict__ tsdfOut,
                                                   float* __restrict__ weight,
                                                   float* __restrict__ tsdfGT) {
    int blk = blockIdx.x;          // 0..16383
    int bp = blk >> 4;             // (b*P + p)
    int chunk = blk & 15;
    int b = bp >> 5;
    int p = bp & 31;

    const float* par = &g_par[bp * 12];
    float qw = par[0];
    float qx = -par[1];            // conjugate for inverse rotation
    float qy = -par[2];
    float qz = -par[3];
    float tx = par[4], ty = par[5], tz = par[6];
    float sx = par[7], sy = par[8], sz = par[9];
    float io = par[10];

    int j0 = chunk * 1024 + threadIdx.x * 4;   // 4 consecutive j (same owner: S=512 ≡ 0 mod 4)
    int o = j0 >> 9;
    int pidx = b * PS + j0;

    float4 X = *reinterpret_cast<const float4*>(&g_px[pidx]);
    float4 Y = *reinterpret_cast<const float4*>(&g_py[pidx]);
    float4 Z = *reinterpret_cast<const float4*>(&g_pz[pidx]);

    float wv = g_par[(b * P + o) * 12 + 11];   // vol[b, owner]
    float gate = (o != p) ? io : 0.0f;

    float4 outv;
    const float* xs = &X.x;
    const float* ys = &Y.x;
    const float* zs = &Z.x;
    float* os = &outv.x;
#pragma unroll
    for (int k = 0; k < 4; k++) {
        float rx = xs[k] - tx;
        float ry = ys[k] - ty;
        float rz = zs[k] - tz;
        float uvx = qy * rz - qz * ry;
        float uvy = qz * rx - qx * rz;
        float uvz = qx * ry - qy * rx;
        float uuvx = qy * uvz - qz * uvy;
        float uuvy = qz * uvx - qx * uvz;
        float uuvz = qx * uvy - qy * uvx;
        float lx = rx + 2.0f * (qw * uvx + uuvx);
        float ly = ry + 2.0f * (qw * uvy + uuvy);
        float lz = rz + 2.0f * (qw * uvz + uuvz);
        float px = fmaxf(sx - fabsf(lx), 0.0f);
        float py = fmaxf(sy - fabsf(ly), 0.0f);
        float pz = fmaxf(sz - fabsf(lz), 0.0f);
        os[k] = (px * px + py * py + pz * pz) * gate;
    }

    size_t base = (size_t)bp * PS + j0;
    *reinterpret_cast<float4*>(&tsdfOut[base]) = outv;
    *reinterpret_cast<float4*>(&weight[base]) = make_float4(wv, wv, wv, wv);
    *reinterpret_cast<float4*>(&tsdfGT[base]) = make_float4(0.f, 0.f, 0.f, 0.f);
}

extern "C" void kernel_launch(void* const* d_in, const int* in_sizes, int n_in,
                              void* d_out, int out_size) {
    const float* shape = (const float*)d_in[0];
    const float* trans = (const float*)d_in[1];
    const float* quat  = (const float*)d_in[2];
    const float* iou   = (const float*)d_in[3];
    const float* coef  = (const float*)d_in[4];
    float* out = (float*)d_out;

    prep_kernel<<<(NBP + 255) / 256, 256>>>(shape, trans, quat, iou);
    points_kernel<<<NPTS / 256, 256>>>(coef);
    tsdf_kernel<<<B * P * 16, 256>>>(out, out + NOUT, out + 2 * NOUT);
}